// round 3
// baseline (speedup 1.0000x reference)
#include <cuda_runtime.h>

// ---------------- problem constants ----------------
#define VOCABN 35
#define PADV   34
#define HID    256
#define NSEQ   128          // B*P = 16*8
#define TT     256          // T
#define TQn    255          // T-1
#define HB     16           // h-indices per CTA
#define NG     16           // h-blocks (NG*HB = HID)
#define SB     16           // sequences per group
#define NSG    8            // sequence groups (NSG*SB = NSEQ)
#define KP     65           // padded K-stride in float4 units (64 real + 1 pad)
#define ROWS7  1792         // 7*HID
#define ARRN   (NSEQ*TQn*HID)   // elements per output array = 8,355,840

// ---------------- device scratch (no allocations allowed) ----------------
__device__ float    g_ztab[VOCABN * ROWS7];      // Emb @ W_x^T + b
__device__ float    g_hbuf[2][NSEQ * HID];       // double-buffered hidden state
__device__ unsigned g_cnt[NSG];                  // group barrier counters (self-resetting)
__device__ unsigned g_gen[NSG];                  // group barrier generations (monotonic)

// packed fp32x2 FMA (Blackwell dual-issue fp32 pipe: 2x scalar FFMA throughput)
__device__ __forceinline__ void ffma2(unsigned long long &d,
                                      unsigned long long a,
                                      unsigned long long b) {
    asm("fma.rn.f32x2 %0, %1, %2, %0;" : "+l"(d) : "l"(a), "l"(b));
}

__device__ __forceinline__ float sigmoidf_(float x) {
    return 1.0f / (1.0f + expf(-x));
}

// ---------------- kernel A: Ztab[v][r] = b[r] + Emb[v,:] . W[r, 0:256] ----------------
// grid = 35 blocks: (rb in 0..6) x (vg in 0..4), 256 threads; thread owns one row r.
__global__ void __launch_bounds__(256) ztab_kernel(const float* __restrict__ Emb,
                                                   const float* __restrict__ W,
                                                   const float* __restrict__ bias) {
    __shared__ float4 sE[7 * KP];   // 7 vocab rows x 64 float4 (padded)
    const int t  = threadIdx.x;
    const int rb = blockIdx.x % 7;
    const int vg = blockIdx.x / 7;
    const int v0 = vg * 7;

    for (int f = t; f < 7 * 64; f += 256) {
        int j = f >> 6, kc = f & 63;
        sE[j * KP + kc] = ((const float4*)Emb)[(v0 + j) * 64 + kc];
    }
    __syncthreads();

    const int r = rb * 256 + t;              // 0..1791
    float acc[7];
    const float bb = bias[r];
#pragma unroll
    for (int j = 0; j < 7; ++j) acc[j] = bb;

    const float4* wr = ((const float4*)W) + (size_t)r * 128;  // row r, cols 0..255
#pragma unroll 4
    for (int kc = 0; kc < 64; ++kc) {
        float4 w = wr[kc];
#pragma unroll
        for (int j = 0; j < 7; ++j) {
            float4 e = sE[j * KP + kc];
            acc[j] += w.x * e.x + w.y * e.y + w.z * e.z + w.w * e.w;
        }
    }
#pragma unroll
    for (int j = 0; j < 7; ++j)
        g_ztab[(v0 + j) * ROWS7 + r] = acc[j];
}

// ---------------- kernel B: persistent reverse scan ----------------
// grid = 128 CTAs = 8 seq-groups x 16 h-blocks. 256 threads: thread = (s = t&15, nb = t>>4).
// Thread owns gate pre-activations for (sequence q0+s, hidden index g*16+nb) and carries
// its cell states c, cbar in registers across all 255 steps.

static const int SMEM_TOTAL = 112 * KP * 16   // sW4: 7*16 rows x 65 float4   = 116480 B
                            + 16  * KP * 16   // sH4: 16 seq  x 65 float4     =  16640 B
                            + VOCABN * 112 * 4 // sZ: ztab slice               =  15680 B
                            + 7 * 256 * 4;    // stg: output staging           =   7168 B

__global__ void __launch_bounds__(256, 1)
scan_kernel(const int*   __restrict__ ev,
            const float* __restrict__ dtime,
            const float* __restrict__ W,
            float*       __restrict__ out) {
    extern __shared__ char smem[];
    float4* sW4 = (float4*)smem;                                   // [(g7*16+nb)][KP]
    float4* sH4 = (float4*)(smem + 112 * KP * 16);                 // [s][KP]
    float*  sZ  = (float*) (smem + 112 * KP * 16 + 16 * KP * 16);  // [v][g7*16+nb]
    float*  stg = sZ + VOCABN * 112;                               // [7][256]

    const int t   = threadIdx.x;
    const int cta = blockIdx.x;
    const int sg  = cta >> 4;        // 0..7 sequence group
    const int g   = cta & 15;        // 0..15 h-block
    const int q0  = sg * SB;
    const int s   = t & 15;          // local sequence
    const int nb  = t >> 4;          // local h index
    const int q   = q0 + s;          // global sequence

    // ---- load persistent W slice: rows g7*256 + g*16 + j, cols 256..511 ----
    for (int f = t; f < 112 * 64; f += 256) {
        int row = f >> 6;            // g7*16 + j
        int kc  = f & 63;
        int g7 = row >> 4, j = row & 15;
        int rg = g7 * HID + g * HB + j;
        sW4[row * KP + kc] = ((const float4*)W)[(size_t)rg * 128 + 64 + kc];
    }
    // ---- load persistent Ztab slice ----
    for (int z = t; z < VOCABN * 112; z += 256) {
        int v = z / 112, rl = z % 112;
        int g7 = rl >> 4, j = rl & 15;
        sZ[z] = g_ztab[v * ROWS7 + g7 * HID + g * HB + j];
    }
    __syncthreads();

    float c_st = 0.0f, cb_st = 0.0f;

    for (int iter = 0; iter < TQn; ++iter) {
        const int tq = TQn - 1 - iter;   // output time index
        const int i  = tq + 1;           // source position

        // ---- stage hidden state of this sequence group into smem ----
        if (iter == 0) {
            for (int f = t; f < 16 * 64; f += 256)
                sH4[(f >> 6) * KP + (f & 63)] = make_float4(0.f, 0.f, 0.f, 0.f);
        } else {
            const float4* hsrc = (const float4*)(g_hbuf[iter & 1] + q0 * HID);
            for (int f = t; f < 16 * 64; f += 256)
                sH4[(f >> 6) * KP + (f & 63)] = hsrc[f];
        }
        __syncthreads();

        const int   v  = ev[q * TT + i];
        const float dt = dtime[q * TT + i];

        // ---- matvec: z[g7] = h . W_h[g7*256 + h_idx, :]  (fp32x2 packed FMA) ----
        unsigned long long acc2[7];
#pragma unroll
        for (int g7 = 0; g7 < 7; ++g7) acc2[g7] = 0ULL;

        const ulonglong2* hp = (const ulonglong2*)(sH4 + s * KP);
        const ulonglong2* wp = (const ulonglong2*)(sW4 + nb * KP);
#pragma unroll 8
        for (int kc = 0; kc < 64; ++kc) {
            ulonglong2 hv = hp[kc];
#pragma unroll
            for (int g7 = 0; g7 < 7; ++g7) {
                ulonglong2 wv = wp[g7 * 16 * KP + kc];
                ffma2(acc2[g7], wv.x, hv.x);
                ffma2(acc2[g7], wv.y, hv.y);
            }
        }

        float za[7];
#pragma unroll
        for (int g7 = 0; g7 < 7; ++g7) {
            float2 p = *(float2*)&acc2[g7];
            za[g7] = p.x + p.y + sZ[v * 112 + g7 * 16 + nb];
        }

        // ---- gates / state update (thread-local) ----
        float gi  = sigmoidf_(za[0]);
        float gf  = sigmoidf_(za[1]);
        float go  = sigmoidf_(za[2]);
        float gz  = tanhf(za[3]);
        float gib = sigmoidf_(za[4]);
        float gfb = sigmoidf_(za[5]);
        float x6  = za[6];
        float gd  = fmaxf(x6, 0.0f) + log1pf(expf(-fabsf(x6)));  // softplus

        float cell   = gf * c_st + gi * gz;
        float cbar   = gfb * cb_st + gib * gz;
        float hminus = go * tanhf(cell);
        float decay  = expf(-gd * dt);
        float cnew   = cbar + (cell - cbar) * decay;
        float hnew   = go * tanhf(cnew);
        float m      = (v != PADV) ? 1.0f : 0.0f;
        cnew *= m;
        float cbarm = cbar * m;
        hnew *= m;
        c_st  = cnew;
        cb_st = cbarm;

        // ---- stage outputs for coalesced 64B stores ----
        const int si = s * 16 + nb;
        stg[0 * 256 + si] = cell;
        stg[1 * 256 + si] = cbarm;
        stg[2 * 256 + si] = gd;
        stg[3 * 256 + si] = go;
        stg[4 * 256 + si] = hnew;
        stg[5 * 256 + si] = hminus;
        stg[6 * 256 + si] = hnew;    // also feeds next step's hidden state
        __syncthreads();

        const int s2 = t >> 4, h2 = t & 15;
        const int ob = ((q0 + s2) * TQn + tq) * HID + g * HB + h2;
#pragma unroll
        for (int a = 0; a < 6; ++a)
            out[a * ARRN + ob] = stg[a * 256 + t];
        g_hbuf[(iter + 1) & 1][(q0 + s2) * HID + g * HB + h2] = stg[6 * 256 + t];

        // ---- per-group barrier (sense-reversal; replay-safe) ----
        __syncthreads();
        if (t == 0) {
            __threadfence();
            volatile unsigned* genp = (volatile unsigned*)&g_gen[sg];
            unsigned my  = *genp;
            unsigned old = atomicAdd(&g_cnt[sg], 1u);
            if (old == NG - 1) {
                atomicExch(&g_cnt[sg], 0u);
                __threadfence();
                atomicAdd(&g_gen[sg], 1u);
            } else {
                while (*genp == my) { }
            }
            __threadfence();
        }
        __syncthreads();
    }
}

// ---------------- launch ----------------
extern "C" void kernel_launch(void* const* d_in, const int* in_sizes, int n_in,
                              void* d_out, int out_size) {
    const int*   ev    = (const int*)  d_in[0];  // event_obs [16,8,256] int32
    const float* dtime = (const float*)d_in[1];  // dtime_obs [16,8,256] f32
    const float* Emb   = (const float*)d_in[2];  // [35,256]
    const float* W     = (const float*)d_in[3];  // [1792,512]
    const float* bias  = (const float*)d_in[4];  // [1792]
    float* out = (float*)d_out;                  // 6 x [128,255,256] f32, concatenated

    ztab_kernel<<<35, 256>>>(Emb, W, bias);

    cudaFuncSetAttribute(scan_kernel,
                         cudaFuncAttributeMaxDynamicSharedMemorySize, SMEM_TOTAL);
    scan_kernel<<<128, 256, SMEM_TOTAL>>>(ev, dtime, W, out);
}

// round 6
// speedup vs baseline: 1.3776x; 1.3776x over previous
#include <cuda_runtime.h>

// ---------------- problem constants ----------------
#define VOCABN 35
#define PADV   34
#define HID    256
#define NSEQ   128
#define TT     256
#define TQn    255
#define HB     16
#define NG     16
#define SB     16
#define NSG    8
#define KP     65
#define ROWS7  1792
#define ARRN   (NSEQ*TQn*HID)
#define PSS    464            // 28*16 + 16 ; PSS mod 32 == 16 -> conflict-free

__device__ float    g_ztab[VOCABN * ROWS7];
__device__ float    g_hbuf[2][NSEQ * HID];
__device__ unsigned g_cnt[NSG];
__device__ unsigned g_gen[NSG];

__device__ __forceinline__ void ffma2(unsigned long long &d,
                                      unsigned long long a,
                                      unsigned long long b) {
    asm("fma.rn.f32x2 %0, %1, %2, %0;" : "+l"(d) : "l"(a), "l"(b));
}
__device__ __forceinline__ float fsig(float x) {
    float e = __expf(-x);
    return __fdividef(1.0f, 1.0f + e);
}
__device__ __forceinline__ float ftanh_(float x) {
    float e = __expf(2.0f * x);
    return 1.0f - __fdividef(2.0f, e + 1.0f);
}

// ---------------- kernel A: Ztab = Emb @ W_x^T + b ----------------
__global__ void __launch_bounds__(256) ztab_kernel(const float* __restrict__ Emb,
                                                   const float* __restrict__ W,
                                                   const float* __restrict__ bias) {
    __shared__ float4 sE[7 * KP];
    const int t  = threadIdx.x;
    const int rb = blockIdx.x % 7;
    const int vg = blockIdx.x / 7;
    const int v0 = vg * 7;

    for (int f = t; f < 7 * 64; f += 256) {
        int j = f >> 6, kc = f & 63;
        sE[j * KP + kc] = ((const float4*)Emb)[(v0 + j) * 64 + kc];
    }
    __syncthreads();

    const int r = rb * 256 + t;
    float acc[7];
    const float bb = bias[r];
#pragma unroll
    for (int j = 0; j < 7; ++j) acc[j] = bb;

    const float4* wr = ((const float4*)W) + (size_t)r * 128;
#pragma unroll 4
    for (int kc = 0; kc < 64; ++kc) {
        float4 w = wr[kc];
#pragma unroll
        for (int j = 0; j < 7; ++j) {
            float4 e = sE[j * KP + kc];
            acc[j] += w.x * e.x + w.y * e.y + w.z * e.z + w.w * e.w;
        }
    }
#pragma unroll
    for (int j = 0; j < 7; ++j)
        g_ztab[(v0 + j) * ROWS7 + r] = acc[j];
}

// ---------------- kernel B: persistent reverse scan, register-blocked ----------------
#define OFF_W   0
#define OFF_H   (112 * KP * 16)
#define OFF_Z   (OFF_H + 16 * KP * 16)
#define OFF_PS  (OFF_Z + VOCABN * 112 * 4)
#define OFF_EV  (OFF_PS + 16 * PSS * 4)
#define OFF_DT  (OFF_EV + 16 * 256 * 4)
static const int SMEM_TOTAL = OFF_DT + 16 * 256 * 4;   // 211264 B

__global__ void __launch_bounds__(256, 1)
scan_kernel(const int*   __restrict__ ev,
            const float* __restrict__ dtime,
            const float* __restrict__ W,
            float*       __restrict__ out) {
    extern __shared__ char smem[];
    float4* sW4 = (float4*)(smem + OFF_W);
    float4* sH4 = (float4*)(smem + OFF_H);
    float*  sZ  = (float*) (smem + OFF_Z);
    float*  ps  = (float*) (smem + OFF_PS);
    int*    sEv = (int*)   (smem + OFF_EV);
    float*  sDt = (float*) (smem + OFF_DT);

    const int t   = threadIdx.x;
    const int cta = blockIdx.x;
    const int sg  = cta >> 4;
    const int g   = cta & 15;
    const int q0  = sg * SB;
    const int nb  = t & 15;
    const int sq  = (t >> 4) & 3;
    const int ks  = t >> 6;
    const int s_g = sq * 4 + ks;
    const int q_g = q0 + s_g;

    // baseline generation (monotonic across graph replays)
    const unsigned gen0 = *((volatile unsigned*)&g_gen[sg]);

    for (int f = t; f < 112 * 64; f += 256) {
        int row = f >> 6, kc = f & 63;
        int g7 = row >> 4, j = row & 15;
        int rg = g7 * HID + g * HB + j;
        sW4[row * KP + kc] = ((const float4*)W)[(size_t)rg * 128 + 64 + kc];
    }
    for (int z = t; z < VOCABN * 112; z += 256) {
        int v = z / 112, rl = z % 112;
        int g7 = rl >> 4, j = rl & 15;
        sZ[z] = g_ztab[v * ROWS7 + g7 * HID + g * HB + j];
    }
    for (int f = t; f < 16 * 256; f += 256) {
        int s = f >> 8, i = f & 255;
        sEv[f] = ev[(q0 + s) * TT + i];
        sDt[f] = dtime[(q0 + s) * TT + i];
    }
    __syncthreads();

    float c_st = 0.0f, cb_st = 0.0f;

    const float4* sWrow = sW4 + nb * KP + ks * 16;
    const float4* sHrow = sH4 + (sq * 4) * KP + ks * 16;
    float* myps = ps + (ks * 4 + sq) * PSS + nb;

    for (int iter = 0; iter < TQn; ++iter) {
        const int tq = TQn - 1 - iter;
        const int i  = tq + 1;

        if (iter == 0) {
            for (int f = t; f < 16 * 64; f += 256)
                sH4[(f >> 6) * KP + (f & 63)] = make_float4(0.f, 0.f, 0.f, 0.f);
        } else {
            const float4* hsrc = (const float4*)(g_hbuf[iter & 1] + q0 * HID);
            for (int f = t; f < 16 * 64; f += 256)
                sH4[(f >> 6) * KP + (f & 63)] = hsrc[f];
        }
        __syncthreads();

        unsigned long long acc[7][4];
#pragma unroll
        for (int g7 = 0; g7 < 7; ++g7)
#pragma unroll
            for (int sl = 0; sl < 4; ++sl) acc[g7][sl] = 0ULL;

#pragma unroll 4
        for (int kc = 0; kc < 16; ++kc) {
            ulonglong2 h0 = ((const ulonglong2*)(sHrow + 0 * KP))[kc];
            ulonglong2 h1 = ((const ulonglong2*)(sHrow + 1 * KP))[kc];
            ulonglong2 h2 = ((const ulonglong2*)(sHrow + 2 * KP))[kc];
            ulonglong2 h3 = ((const ulonglong2*)(sHrow + 3 * KP))[kc];
#pragma unroll
            for (int g7 = 0; g7 < 7; ++g7) {
                ulonglong2 wv = ((const ulonglong2*)(sWrow + g7 * (16 * KP)))[kc];
                ffma2(acc[g7][0], wv.x, h0.x); ffma2(acc[g7][0], wv.y, h0.y);
                ffma2(acc[g7][1], wv.x, h1.x); ffma2(acc[g7][1], wv.y, h1.y);
                ffma2(acc[g7][2], wv.x, h2.x); ffma2(acc[g7][2], wv.y, h2.y);
                ffma2(acc[g7][3], wv.x, h3.x); ffma2(acc[g7][3], wv.y, h3.y);
            }
        }

#pragma unroll
        for (int g7 = 0; g7 < 7; ++g7)
#pragma unroll
            for (int sl = 0; sl < 4; ++sl) {
                float2 p = *(float2*)&acc[g7][sl];
                myps[(sl * 7 + g7) * 16] = p.x + p.y;
            }
        __syncthreads();

        const int   v  = sEv[s_g * 256 + i];
        const float dt = sDt[s_g * 256 + i];

        float za[7];
        const float* zb = sZ + v * 112 + nb;
#pragma unroll
        for (int g7 = 0; g7 < 7; ++g7) {
            float sum = zb[g7 * 16];
#pragma unroll
            for (int kk = 0; kk < 4; ++kk)
                sum += ps[(kk * 4 + sq) * PSS + (ks * 7 + g7) * 16 + nb];
            za[g7] = sum;
        }

        float gi  = fsig(za[0]);
        float gf  = fsig(za[1]);
        float go  = fsig(za[2]);
        float gz  = ftanh_(za[3]);
        float gib = fsig(za[4]);
        float gfb = fsig(za[5]);
        float x6  = za[6];
        float gd  = fmaxf(x6, 0.0f) + log1pf(__expf(-fabsf(x6)));

        float cell   = gf * c_st + gi * gz;
        float cbar   = gfb * cb_st + gib * gz;
        float hminus = go * ftanh_(cell);
        float decay  = __expf(-gd * dt);
        float cnew   = cbar + (cell - cbar) * decay;
        float hnew   = go * ftanh_(cnew);
        float m      = (v != PADV) ? 1.0f : 0.0f;
        cnew *= m;
        float cbarm = cbar * m;
        hnew *= m;
        c_st  = cnew;
        cb_st = cbarm;

        // publish hidden state, arrive at group barrier
        g_hbuf[(iter + 1) & 1][q_g * HID + g * HB + nb] = hnew;
        __syncthreads();
        if (t == 0) {
            __threadfence();
            unsigned old = atomicAdd(&g_cnt[sg], 1u);
            if (old == NG - 1) {
                atomicExch(&g_cnt[sg], 0u);
                __threadfence();
                atomicAdd(&g_gen[sg], 1u);
            }
        }

        // overlap output stores with the inter-CTA sync
        const int ob = (q_g * TQn + tq) * HID + g * HB + nb;
        out[0 * ARRN + ob] = cell;
        out[1 * ARRN + ob] = cbarm;
        out[2 * ARRN + ob] = gd;
        out[3 * ARRN + ob] = go;
        out[4 * ARRN + ob] = hnew;
        out[5 * ARRN + ob] = hminus;

        if (t == 0) {
            volatile unsigned* genp = (volatile unsigned*)&g_gen[sg];
            const unsigned need = (unsigned)(iter + 1);
            while ((*genp - gen0) < need) { }
            __threadfence();
        }
        __syncthreads();
    }
}

// ---------------- launch ----------------
extern "C" void kernel_launch(void* const* d_in, const int* in_sizes, int n_in,
                              void* d_out, int out_size) {
    const int*   ev    = (const int*)  d_in[0];
    const float* dtime = (const float*)d_in[1];
    const float* Emb   = (const float*)d_in[2];
    const float* W     = (const float*)d_in[3];
    const float* bias  = (const float*)d_in[4];
    float* out = (float*)d_out;

    ztab_kernel<<<35, 256>>>(Emb, W, bias);

    cudaFuncSetAttribute(scan_kernel,
                         cudaFuncAttributeMaxDynamicSharedMemorySize, SMEM_TOTAL);
    scan_kernel<<<128, 256, SMEM_TOTAL>>>(ev, dtime, W, out);
}